// round 11
// baseline (speedup 1.0000x reference)
#include <cuda_runtime.h>
#include <cuda_bf16.h>
#include <math.h>
#include <stdint.h>

#define NUM      512
#define DH       64
#define EMAX     4096
#define PADMAX   4608          // EMAX + up to NUM pad edges (even-length segments)
#define MAIN_N   10
#define THREADS  1024
#define ZSTR     264           // z / h2 row stride bytes
#define ASTR     144           // A / B tile row stride bytes (36 words: conflict-free)

// ------------------------- device scratch (no allocs allowed) ----------------
__device__ int2           g_csr[PADMAX];   // {r*ZSTR, coef bits}; pads = {0,0}
__device__ unsigned short g_row[PADMAX];   // plain r (layer 3)
__device__ int            g_ptr[NUM + 1];  // padded segment starts (even)
__device__ float          g_EW1[NUM * DH];
__device__ uint32_t       g_BT2hi[DH * DH / 2];  // W2^T hi, [n][k] bf16x2
__device__ uint32_t       g_BT2lo[DH * DH / 2];  // W2^T lo

// ------------------------- mma helpers (sm_80+ PTX, works on bare sm_103) ----
static __device__ __forceinline__ void ldm4(uint32_t* r, uint32_t addr){
    asm volatile("ldmatrix.sync.aligned.m8n8.x4.shared.b16 {%0,%1,%2,%3}, [%4];"
                 : "=r"(r[0]), "=r"(r[1]), "=r"(r[2]), "=r"(r[3]) : "r"(addr));
}
static __device__ __forceinline__ void mma_bf16(float& c0, float& c1, float& c2, float& c3,
                                                const uint32_t* a, uint32_t b0, uint32_t b1){
    asm volatile("mma.sync.aligned.m16n8k16.row.col.f32.bf16.bf16.f32 "
                 "{%0,%1,%2,%3}, {%4,%5,%6,%7}, {%8,%9}, {%0,%1,%2,%3};"
                 : "+f"(c0), "+f"(c1), "+f"(c2), "+f"(c3)
                 : "r"(a[0]), "r"(a[1]), "r"(a[2]), "r"(a[3]), "r"(b0), "r"(b1));
}

// ------------------------- unified prep: EW1 / W2-split / graph --------------
#define PS_CS    0
#define PS_RS    16384
#define PS_CNT   32768
#define PS_DEG   163840
#define PS_DINV  165888
#define PS_SPTR  167936
#define PS_TOTAL 170000

__global__ void __launch_bounds__(1024)
prep_all(const float* __restrict__ emb, const float* __restrict__ W1,
         const float* __restrict__ W2,
         const int* __restrict__ erow, const int* __restrict__ ecol, int E)
{
    const int blk = blockIdx.x;
    if (blk < 32){
        int i = blk * 1024 + threadIdx.x;            // n*64 + d
        int n = i >> 6, d = i & 63;
        float acc = 0.f;
#pragma unroll
        for (int k = 0; k < DH; k++) acc += emb[n * DH + k] * W1[k * DH + d];
        g_EW1[i] = acc;
        return;
    }
    if (blk == 32){
        for (int idx = threadIdx.x; idx < DH * DH / 2; idx += 1024){
            int o = idx >> 5, kp = idx & 31;         // n=o, k pair 2kp,2kp+1
            float w0 = W2[(2 * kp) * DH + o];
            float w1 = W2[(2 * kp + 1) * DH + o];
            __nv_bfloat162 hi = __float22bfloat162_rn(make_float2(w0, w1));
            float r0 = w0 - __bfloat162float(hi.x);
            float r1 = w1 - __bfloat162float(hi.y);
            __nv_bfloat162 lo = __float22bfloat162_rn(make_float2(r0, r1));
            g_BT2hi[idx] = *(uint32_t*)&hi;
            g_BT2lo[idx] = *(uint32_t*)&lo;
        }
        return;
    }

    // ---- graph -> stable col-sorted CSR, even-padded segments -------------------
    extern __shared__ char psm[];
    int*            cs   = (int*)(psm + PS_CS);
    int*            rs   = (int*)(psm + PS_RS);
    unsigned short* cnt  = (unsigned short*)(psm + PS_CNT);
    int*            deg  = (int*)(psm + PS_DEG);
    float*          dinv = (float*)(psm + PS_DINV);
    int*            sptr = (int*)(psm + PS_SPTR);

    const int t  = threadIdx.x;
    const int wd = t >> 5;
    const int ln = t & 31;

    for (int e = t; e < EMAX; e += 1024){
        cs[e] = (e < E) ? ecol[e] : -1;
        rs[e] = (e < E) ? erow[e] : 0;
    }
    for (int i = t; i < PADMAX; i += 1024){          // zero pads (coef=0 edges)
        g_csr[i] = make_int2(0, 0);
        g_row[i] = 0;
    }
    for (int i = t; i < (128 * NUM) / 2; i += 1024)
        ((unsigned*)cnt)[i] = 0;
    __syncthreads();

    for (int ck = wd; ck < 128; ck += 32){
        int col = cs[ck * 32 + ln];
        unsigned mask = __match_any_sync(0xffffffffu, col);
        if (col >= 0 && ln == (__ffs(mask) - 1))
            cnt[ck * NUM + col] = (unsigned short)__popc(mask);
    }
    __syncthreads();

    if (t < NUM){
        int run = 0;
#pragma unroll 4
        for (int k = 0; k < 128; k++){
            int v = cnt[k * NUM + t];
            cnt[k * NUM + t] = (unsigned short)run;
            run += v;
        }
        deg[t]  = run;                                // real degree (for dinv)
        dinv[t] = run > 0 ? rsqrtf((float)run) : 0.f;
    }
    __syncthreads();
    if (t == 0){
        int s = 0;
        for (int n = 0; n < NUM; n++){
            sptr[n] = s;
            s += (deg[n] + 1) & ~1;                   // even-padded segment length
        }
        sptr[NUM] = s;
    }
    __syncthreads();

    for (int ck = wd; ck < 128; ck += 32){
        int e   = ck * 32 + ln;
        int col = cs[e];
        unsigned mask = __match_any_sync(0xffffffffu, col);
        int rank = __popc(mask & ((1u << ln) - 1u));
        if (col >= 0){
            int r   = rs[e];
            int pos = sptr[col] + (int)cnt[ck * NUM + col] + rank;
            g_csr[pos] = make_int2(r * ZSTR, __float_as_int(dinv[col] * dinv[r]));
            g_row[pos] = (unsigned short)r;
        }
    }
    if (t <= NUM) g_ptr[t] = sptr[t];
}

// ------------------------- fused GCN mega-kernel (one CTA per batch) ----------
// smem layout (bytes):
//   region0: z[512x264]=135168 -> A_hi[512x144]@0 + A_lo @73728 -> h2[512x264]
//   meta [4608] int2  @ 147456 (36864)   {r*ZSTR, coef}, pads coef=0
//   sptr [513]  i32   @ 184320 ( 2052) +pad
//   xs   [512]  f32   @ 186376 ( 2048)
//   t3   [512]  f32   @ 188424 ( 2048)
//   lg   [512]  f32   @ 190472 ( 2048)
//   B_hi [64x144]     @ 192544 ( 9216)
//   B_lo [64x144]     @ 201760 ( 9216)
//   row3 [4608] u16   @ 210976 ( 9216)
#define SM_A_HI  0
#define SM_A_LO  73728
#define SM_META  147456
#define SM_PTR   184320
#define SM_XS    186376
#define SM_T3    188424
#define SM_LG    190472
#define SM_BHI   192544
#define SM_BLO   201760
#define SM_ROW3  210976
#define SM_TOTAL 220192

static __device__ __forceinline__ uint32_t smem_u32(const void* p){
    uint32_t a;
    asm("{ .reg .u64 t; cvta.to.shared.u64 t, %1; cvt.u32.u64 %0, t; }"
        : "=r"(a) : "l"(p));
    return a;
}

__global__ void __launch_bounds__(THREADS, 1)
gcn_mega(const float* __restrict__ x,
         const float* __restrict__ b1,
         const float* __restrict__ b2,
         const float* __restrict__ W3,
         const float* __restrict__ b3,
         float* __restrict__ out)
{
    extern __shared__ char smraw[];
    int2*           meta = (int2*)(smraw + SM_META);
    int*            sptr = (int*)(smraw + SM_PTR);
    float*          xs   = (float*)(smraw + SM_XS);
    float*          t3   = (float*)(smraw + SM_T3);
    float*          lg   = (float*)(smraw + SM_LG);
    unsigned short* row3 = (unsigned short*)(smraw + SM_ROW3);

    const uint32_t sbase = smem_u32(smraw);
    const int t  = threadIdx.x;
    const int b  = blockIdx.x;
    const int ln = t & 31;               // lane
    const int gw = t >> 5;               // warp id 0..31
    const int loff = 8 * ln;             // this lane's dim-pair byte offset

    // ---- stage graph meta + x + B tiles ----------------------------------------
    {
        const int2* gc = g_csr;
#pragma unroll
        for (int e = t; e < PADMAX; e += THREADS)
            meta[e] = gc[e];                           // pads staged as {0,0}
        const uint32_t* gr = (const uint32_t*)g_row;
#pragma unroll
        for (int i = t; i < PADMAX / 2; i += THREADS)
            ((uint32_t*)row3)[i] = gr[i];
        if (t <= NUM) sptr[t] = g_ptr[t];
        if (t < NUM)  xs[t] = x[b * NUM + t];
#pragma unroll
        for (int i = t; i < DH * DH / 2; i += THREADS){
            int n = i >> 5, kp = i & 31;
            *(uint32_t*)(smraw + SM_BHI + n * ASTR + 4 * kp) = g_BT2hi[i];
            *(uint32_t*)(smraw + SM_BLO + n * ASTR + 4 * kp) = g_BT2lo[i];
        }
    }
    __syncthreads();

    // ---- z = diag(x) * EW1 (float2, stride 264) ---------------------------------
    {
        const float2* ew2 = (const float2*)g_EW1;
#pragma unroll
        for (int k = 0; k < (NUM * 32) / THREADS; k++){
            int i = t + k * THREADS;            // n*32 + jp
            int n = i >> 5, jp = i & 31;
            float xv = xs[n];
            float2 w = ew2[i];
            *(float2*)(smraw + n * ZSTR + 8 * jp) = make_float2(xv * w.x, xv * w.y);
        }
    }
    __syncthreads();

    // ---- layer 1 agg into registers: warp gw owns nodes gw+32m ------------------
    float2 h1[16];
    {
        float b1x = b1[2 * ln], b1y = b1[2 * ln + 1];
#pragma unroll
        for (int m = 0; m < 16; m++){
            int n = gw + 32 * m;
            int e0 = sptr[n], e1 = sptr[n + 1];        // both even
            float a0 = 0.f, a1 = 0.f, a2 = 0.f, a3 = 0.f;
#pragma unroll 2
            for (int e = e0; e < e1; e += 2){
                int4  mm = *(const int4*)(meta + e);   // 2 edges, LDS.128 bcast
                float c0 = __int_as_float(mm.y);
                float c1 = __int_as_float(mm.w);
                float2 z0 = *(const float2*)(smraw + mm.x + loff);
                float2 z1 = *(const float2*)(smraw + mm.z + loff);
                a0 += c0 * z0.x; a1 += c0 * z0.y;
                a2 += c1 * z1.x; a3 += c1 * z1.y;
            }
            a0 += a2; a1 += a3;
            h1[m] = make_float2(fmaxf(a0 + b1x, 0.f), fmaxf(a1 + b1y, 0.f));
        }
    }
    __syncthreads();                      // all z reads complete (z dead)

    // ---- write h1 as bf16 hi/lo A tiles (overwrites z; 144B stride) -------------
#pragma unroll
    for (int m = 0; m < 16; m++){
        int n = gw + 32 * m;
        float2 v = h1[m];
        __nv_bfloat162 hi2 = __float22bfloat162_rn(v);
        float2 r = make_float2(v.x - __bfloat162float(hi2.x),
                               v.y - __bfloat162float(hi2.y));
        __nv_bfloat162 lo2 = __float22bfloat162_rn(r);
        *(__nv_bfloat162*)(smraw + SM_A_HI + n * ASTR + 4 * ln) = hi2;
        *(__nv_bfloat162*)(smraw + SM_A_LO + n * ASTR + 4 * ln) = lo2;
    }
    __syncthreads();

    // ---- load A fragments (warp w: rows 16w..16w+15, k 0..63, hi+lo) ------------
    uint32_t ah[16], al[16];
    {
        uint32_t abase = sbase + (16 * gw + (ln & 15)) * ASTR + ((ln >> 4) << 4);
#pragma unroll
        for (int kt = 0; kt < 4; kt++) ldm4(&ah[4 * kt], abase + SM_A_HI + 32 * kt);
#pragma unroll
        for (int kt = 0; kt < 4; kt++) ldm4(&al[4 * kt], abase + SM_A_LO + 32 * kt);
    }
    __syncthreads();                      // all A reads done; region reusable as h2

    // ---- h2 = h1 @ W2: 8 n-tiles x 4 k-tiles x 3 passes of mma.m16n8k16 ---------
    {
        const int rowa = 16 * gw + (ln >> 2);
#pragma unroll 1
        for (int nt = 0; nt < 8; nt++){
            float c0 = 0.f, c1 = 0.f, c2 = 0.f, c3 = 0.f;
            uint32_t boff = (uint32_t)((8 * nt + (ln >> 2)) * ASTR + 4 * (ln & 3));
#pragma unroll
            for (int kt = 0; kt < 4; kt++){
                uint32_t b0h = *(const uint32_t*)(smraw + SM_BHI + boff + 32 * kt);
                uint32_t b1h = *(const uint32_t*)(smraw + SM_BHI + boff + 32 * kt + 16);
                uint32_t b0l = *(const uint32_t*)(smraw + SM_BLO + boff + 32 * kt);
                uint32_t b1l = *(const uint32_t*)(smraw + SM_BLO + boff + 32 * kt + 16);
                mma_bf16(c0, c1, c2, c3, &ah[4 * kt], b0h, b1h);
                mma_bf16(c0, c1, c2, c3, &ah[4 * kt], b0l, b1l);
                mma_bf16(c0, c1, c2, c3, &al[4 * kt], b0h, b1h);
            }
            *(float2*)(smraw + rowa * ZSTR + 32 * nt + 8 * (ln & 3)) = make_float2(c0, c1);
            *(float2*)(smraw + (rowa + 8) * ZSTR + 32 * nt + 8 * (ln & 3)) = make_float2(c2, c3);
        }
    }
    __syncthreads();

    // ---- layer 2 agg + relu + W3 dot --------------------------------------------
    {
        float b2x = b2[2 * ln], b2y = b2[2 * ln + 1];
        float w3x = W3[2 * ln], w3y = W3[2 * ln + 1];
#pragma unroll
        for (int m = 0; m < 16; m++){
            int n = gw + 32 * m;
            int e0 = sptr[n], e1 = sptr[n + 1];
            float a0 = 0.f, a1 = 0.f, a2 = 0.f, a3 = 0.f;
#pragma unroll 2
            for (int e = e0; e < e1; e += 2){
                int4  mm = *(const int4*)(meta + e);
                float c0 = __int_as_float(mm.y);
                float c1 = __int_as_float(mm.w);
                float2 h0 = *(const float2*)(smraw + mm.x + loff);
                float2 hv = *(const float2*)(smraw + mm.z + loff);
                a0 += c0 * h0.x; a1 += c0 * h0.y;
                a2 += c1 * hv.x; a3 += c1 * hv.y;
            }
            a0 = fmaxf(a0 + a2 + b2x, 0.f);
            a1 = fmaxf(a1 + a3 + b2y, 0.f);
            float v = a0 * w3x + a1 * w3y;
#pragma unroll
            for (int o = 16; o > 0; o >>= 1) v += __shfl_xor_sync(0xffffffffu, v, o);
            if (ln == 0) t3[n] = v;
        }
    }
    __syncthreads();

    // ---- layer 3 aggregation: logits ----------------------------------------------
    if (t < NUM){
        float a = b3[0];
        int e0 = sptr[t], e1 = sptr[t + 1];
#pragma unroll 4
        for (int e = e0; e < e1; e++)
            a += __int_as_float(meta[e].y) * t3[row3[e]];
        lg[t] = a;
    }
    __syncthreads();

    // ---- softmax over [0,10), sigmoid elsewhere ------------------------------------
    if (t < NUM){
        float v = lg[t];
        if (t < 32){
            float xv = (t < MAIN_N) ? v : -INFINITY;
            float m = xv;
#pragma unroll
            for (int o = 16; o > 0; o >>= 1) m = fmaxf(m, __shfl_xor_sync(0xffffffffu, m, o));
            float p = (t < MAIN_N) ? expf(xv - m) : 0.f;
            float s = p;
#pragma unroll
            for (int o = 16; o > 0; o >>= 1) s += __shfl_xor_sync(0xffffffffu, s, o);
            if (t < MAIN_N) out[b * NUM + t] = p / s;
        }
        if (t >= MAIN_N) out[b * NUM + t] = 1.f / (1.f + expf(-v));
    }
}

// ------------------------- launcher ------------------------------------------
extern "C" void kernel_launch(void* const* d_in, const int* in_sizes, int n_in,
                              void* d_out, int out_size)
{
    const float* x    = (const float*)d_in[0];
    const float* emb  = (const float*)d_in[1];
    const float* W1   = (const float*)d_in[2];
    const float* b1   = (const float*)d_in[3];
    const float* W2   = (const float*)d_in[4];
    const float* b2   = (const float*)d_in[5];
    const float* W3   = (const float*)d_in[6];
    const float* b3   = (const float*)d_in[7];
    const int*  erow  = (const int*)d_in[8];
    const int*  ecol  = (const int*)d_in[9];
    float* out = (float*)d_out;

    const int E = in_sizes[8];
    const int B = in_sizes[0] / NUM;

    cudaFuncSetAttribute(gcn_mega, cudaFuncAttributeMaxDynamicSharedMemorySize, SM_TOTAL);
    cudaFuncSetAttribute(prep_all, cudaFuncAttributeMaxDynamicSharedMemorySize, PS_TOTAL);

    prep_all<<<34, 1024, PS_TOTAL>>>(emb, W1, W2, erow, ecol, E);
    gcn_mega<<<B, THREADS, SM_TOTAL>>>(x, b1, b2, W3, b3, out);

    (void)n_in; (void)out_size;
}

// round 12
// speedup vs baseline: 1.0600x; 1.0600x over previous
#include <cuda_runtime.h>
#include <cuda_bf16.h>
#include <math.h>
#include <stdint.h>

#define NUM      512
#define DH       64
#define EMAX     4096
#define MAIN_N   10
#define THREADS  1024
#define ZSTR     264           // z / h2 row stride bytes
#define ASTR     144           // A / B tile row stride bytes (36 words: conflict-free)

// ------------------------- device scratch (no allocs allowed) ----------------
__device__ __align__(16) int2 g_csr[EMAX];  // {row, coef bits} col-sorted, stable
__device__ int       g_ptr[NUM + 1];
__device__ float     g_EW1[NUM * DH];
__device__ uint32_t  g_BT2hi[DH * DH / 2];  // W2^T hi, [n][k] packed bf16x2
__device__ uint32_t  g_BT2lo[DH * DH / 2];  // W2^T lo

// ------------------------- mma / cp.async helpers ----------------------------
static __device__ __forceinline__ void ldm4(uint32_t* r, uint32_t addr){
    asm volatile("ldmatrix.sync.aligned.m8n8.x4.shared.b16 {%0,%1,%2,%3}, [%4];"
                 : "=r"(r[0]), "=r"(r[1]), "=r"(r[2]), "=r"(r[3]) : "r"(addr));
}
static __device__ __forceinline__ void mma_bf16(float& c0, float& c1, float& c2, float& c3,
                                                const uint32_t* a, uint32_t b0, uint32_t b1){
    asm volatile("mma.sync.aligned.m16n8k16.row.col.f32.bf16.bf16.f32 "
                 "{%0,%1,%2,%3}, {%4,%5,%6,%7}, {%8,%9}, {%0,%1,%2,%3};"
                 : "+f"(c0), "+f"(c1), "+f"(c2), "+f"(c3)
                 : "r"(a[0]), "r"(a[1]), "r"(a[2]), "r"(a[3]), "r"(b0), "r"(b1));
}
static __device__ __forceinline__ void cpa16(uint32_t dst, const void* src){
    asm volatile("cp.async.cg.shared.global [%0], [%1], 16;" :: "r"(dst), "l"(src));
}
static __device__ __forceinline__ void cpa4(uint32_t dst, const void* src){
    asm volatile("cp.async.ca.shared.global [%0], [%1], 4;" :: "r"(dst), "l"(src));
}

// ------------------------- unified prep: EW1 / W2-split / graph --------------
#define PS_CS    0
#define PS_RS    16384
#define PS_CNT   32768
#define PS_DEG   163840
#define PS_DINV  165888
#define PS_SPTR  167936
#define PS_TOTAL 170000

__global__ void __launch_bounds__(1024)
prep_all(const float* __restrict__ emb, const float* __restrict__ W1,
         const float* __restrict__ W2,
         const int* __restrict__ erow, const int* __restrict__ ecol, int E)
{
    const int blk = blockIdx.x;
    if (blk < 32){
        int i = blk * 1024 + threadIdx.x;            // n*64 + d
        int n = i >> 6, d = i & 63;
        float acc = 0.f;
#pragma unroll
        for (int k = 0; k < DH; k++) acc += emb[n * DH + k] * W1[k * DH + d];
        g_EW1[i] = acc;
        return;
    }
    if (blk == 32){
        for (int idx = threadIdx.x; idx < DH * DH / 2; idx += 1024){
            int o = idx >> 5, kp = idx & 31;         // n=o, k pair 2kp,2kp+1
            float w0 = W2[(2 * kp) * DH + o];
            float w1 = W2[(2 * kp + 1) * DH + o];
            __nv_bfloat162 hi = __float22bfloat162_rn(make_float2(w0, w1));
            float r0 = w0 - __bfloat162float(hi.x);
            float r1 = w1 - __bfloat162float(hi.y);
            __nv_bfloat162 lo = __float22bfloat162_rn(make_float2(r0, r1));
            g_BT2hi[idx] = *(uint32_t*)&hi;
            g_BT2lo[idx] = *(uint32_t*)&lo;
        }
        return;
    }

    // ---- graph -> stable col-sorted CSR -----------------------------------------
    extern __shared__ char psm[];
    int*            cs   = (int*)(psm + PS_CS);
    int*            rs   = (int*)(psm + PS_RS);
    unsigned short* cnt  = (unsigned short*)(psm + PS_CNT);
    int*            deg  = (int*)(psm + PS_DEG);
    float*          dinv = (float*)(psm + PS_DINV);
    int*            sptr = (int*)(psm + PS_SPTR);

    const int t  = threadIdx.x;
    const int wd = t >> 5;
    const int ln = t & 31;

    for (int e = t; e < EMAX; e += 1024){
        cs[e] = (e < E) ? ecol[e] : -1;
        rs[e] = (e < E) ? erow[e] : 0;
        g_csr[e] = make_int2(0, 0);                  // zero (pads stay coef=0)
    }
    for (int i = t; i < (128 * NUM) / 2; i += 1024)
        ((unsigned*)cnt)[i] = 0;
    __syncthreads();

    for (int ck = wd; ck < 128; ck += 32){
        int col = cs[ck * 32 + ln];
        unsigned mask = __match_any_sync(0xffffffffu, col);
        if (col >= 0 && ln == (__ffs(mask) - 1))
            cnt[ck * NUM + col] = (unsigned short)__popc(mask);
    }
    __syncthreads();

    if (t < NUM){
        int run = 0;
#pragma unroll 4
        for (int k = 0; k < 128; k++){
            int v = cnt[k * NUM + t];
            cnt[k * NUM + t] = (unsigned short)run;
            run += v;
        }
        deg[t]  = run;
        dinv[t] = run > 0 ? rsqrtf((float)run) : 0.f;
    }
    __syncthreads();
    if (t == 0){
        int s = 0;
        for (int n = 0; n < NUM; n++){ sptr[n] = s; s += deg[n]; }
        sptr[NUM] = s;
    }
    __syncthreads();

    for (int ck = wd; ck < 128; ck += 32){
        int e   = ck * 32 + ln;
        int col = cs[e];
        unsigned mask = __match_any_sync(0xffffffffu, col);
        int rank = __popc(mask & ((1u << ln) - 1u));
        if (col >= 0){
            int r   = rs[e];
            int pos = sptr[col] + (int)cnt[ck * NUM + col] + rank;
            g_csr[pos] = make_int2(r, __float_as_int(dinv[col] * dinv[r]));
        }
    }
    if (t <= NUM) g_ptr[t] = sptr[t];
}

// ------------------------- fused GCN mega-kernel (one CTA per batch) ----------
// smem layout (bytes):
//   region0: z[512x264]=135168 -> A_hi[512x144]@0 + A_lo @73728 -> h2[512x264]
//   meta [4096] int2  @ 147456 (32768)   {r, coef}
//   sptr [513]  i32   @ 180224 ( 2052) +pad
//   t3   [512]  f32   @ 184328 ( 2048)
//   lg   [512]  f32   @ 186376 ( 2048)
//   B_hi [64x144]     @ 188432 ( 9216)
//   B_lo [64x144]     @ 197648 ( 9216)
#define SM_A_HI  0
#define SM_A_LO  73728
#define SM_META  147456
#define SM_PTR   180224
#define SM_T3    184328
#define SM_LG    186376
#define SM_BHI   188432
#define SM_BLO   197648
#define SM_TOTAL 206864

static __device__ __forceinline__ uint32_t smem_u32(const void* p){
    uint32_t a;
    asm("{ .reg .u64 t; cvta.to.shared.u64 t, %1; cvt.u32.u64 %0, t; }"
        : "=r"(a) : "l"(p));
    return a;
}

__global__ void __launch_bounds__(THREADS, 1)
gcn_mega(const float* __restrict__ x,
         const float* __restrict__ b1,
         const float* __restrict__ b2,
         const float* __restrict__ W3,
         const float* __restrict__ b3,
         float* __restrict__ out)
{
    extern __shared__ char smraw[];
    int2*  meta = (int2*)(smraw + SM_META);
    int*   sptr = (int*)(smraw + SM_PTR);
    float* t3   = (float*)(smraw + SM_T3);
    float* lg   = (float*)(smraw + SM_LG);

    const uint32_t sbase = smem_u32(smraw);
    const int t  = threadIdx.x;
    const int b  = blockIdx.x;
    const int ln = t & 31;               // lane
    const int gw = t >> 5;               // warp id 0..31

    // ---- async-stage meta + B tiles; then z-build overlapped --------------------
    {
#pragma unroll
        for (int i = t; i < EMAX / 2; i += THREADS)           // 16B chunks
            cpa16(sbase + SM_META + 16 * i, (const char*)g_csr + 16 * i);
#pragma unroll
        for (int i = t; i < DH * DH / 2; i += THREADS){
            int n = i >> 5, kp = i & 31;
            cpa4(sbase + SM_BHI + n * ASTR + 4 * kp, &g_BT2hi[i]);
            cpa4(sbase + SM_BLO + n * ASTR + 4 * kp, &g_BT2lo[i]);
        }
        asm volatile("cp.async.commit_group;");
        if (t <= NUM) sptr[t] = g_ptr[t];

        // z = diag(x) * EW1 (x is a per-warp broadcast LDG; no xs staging)
        const float2* ew2 = (const float2*)g_EW1;
#pragma unroll
        for (int k = 0; k < (NUM * 32) / THREADS; k++){
            int i = t + k * THREADS;            // n*32 + jp
            int n = i >> 5, jp = i & 31;
            float xv = __ldg(x + b * NUM + n);  // all lanes same n -> broadcast
            float2 w = ew2[i];
            *(float2*)(smraw + n * ZSTR + 8 * jp) = make_float2(xv * w.x, xv * w.y);
        }
        asm volatile("cp.async.wait_group 0;");
    }
    __syncthreads();

    // ---- layer 1 agg into registers: warp gw owns nodes gw+32m ------------------
    float2 h1[16];
    {
        float b1x = b1[2 * ln], b1y = b1[2 * ln + 1];
#pragma unroll
        for (int m = 0; m < 16; m++){
            int n = gw + 32 * m;
            int e0 = sptr[n], e1 = sptr[n + 1];
            float a0 = 0.f, a1 = 0.f;
#pragma unroll 4
            for (int e = e0; e < e1; e++){
                int2  rc = meta[e];                        // LDS.64 broadcast
                float c  = __int_as_float(rc.y);
                float2 zv = *(const float2*)(smraw + rc.x * ZSTR + 8 * ln);
                a0 += c * zv.x;
                a1 += c * zv.y;
            }
            h1[m] = make_float2(fmaxf(a0 + b1x, 0.f), fmaxf(a1 + b1y, 0.f));
        }
    }
    __syncthreads();                      // all z reads complete (z dead)

    // ---- write h1 as bf16 hi/lo A tiles (overwrites z; 144B stride) -------------
#pragma unroll
    for (int m = 0; m < 16; m++){
        int n = gw + 32 * m;
        float2 v = h1[m];
        __nv_bfloat162 hi2 = __float22bfloat162_rn(v);
        float2 r = make_float2(v.x - __bfloat162float(hi2.x),
                               v.y - __bfloat162float(hi2.y));
        __nv_bfloat162 lo2 = __float22bfloat162_rn(r);
        *(__nv_bfloat162*)(smraw + SM_A_HI + n * ASTR + 4 * ln) = hi2;
        *(__nv_bfloat162*)(smraw + SM_A_LO + n * ASTR + 4 * ln) = lo2;
    }
    __syncthreads();

    // ---- load A fragments (warp w: rows 16w..16w+15, k 0..63, hi+lo) ------------
    uint32_t ah[16], al[16];
    {
        uint32_t abase = sbase + (16 * gw + (ln & 15)) * ASTR + ((ln >> 4) << 4);
#pragma unroll
        for (int kt = 0; kt < 4; kt++) ldm4(&ah[4 * kt], abase + SM_A_HI + 32 * kt);
#pragma unroll
        for (int kt = 0; kt < 4; kt++) ldm4(&al[4 * kt], abase + SM_A_LO + 32 * kt);
    }
    __syncthreads();                      // all A reads done; region reusable as h2

    // ---- h2 = h1 @ W2: 8 n-tiles x 4 k-tiles x 3 passes of mma.m16n8k16 ---------
    {
        const int rowa = 16 * gw + (ln >> 2);
#pragma unroll 1
        for (int nt = 0; nt < 8; nt++){
            float c0 = 0.f, c1 = 0.f, c2 = 0.f, c3 = 0.f;
            uint32_t boff = (uint32_t)((8 * nt + (ln >> 2)) * ASTR + 4 * (ln & 3));
#pragma unroll
            for (int kt = 0; kt < 4; kt++){
                uint32_t b0h = *(const uint32_t*)(smraw + SM_BHI + boff + 32 * kt);
                uint32_t b1h = *(const uint32_t*)(smraw + SM_BHI + boff + 32 * kt + 16);
                uint32_t b0l = *(const uint32_t*)(smraw + SM_BLO + boff + 32 * kt);
                uint32_t b1l = *(const uint32_t*)(smraw + SM_BLO + boff + 32 * kt + 16);
                mma_bf16(c0, c1, c2, c3, &ah[4 * kt], b0h, b1h);
                mma_bf16(c0, c1, c2, c3, &ah[4 * kt], b0l, b1l);
                mma_bf16(c0, c1, c2, c3, &al[4 * kt], b0h, b1h);
            }
            *(float2*)(smraw + rowa * ZSTR + 32 * nt + 8 * (ln & 3)) = make_float2(c0, c1);
            *(float2*)(smraw + (rowa + 8) * ZSTR + 32 * nt + 8 * (ln & 3)) = make_float2(c2, c3);
        }
    }
    __syncthreads();

    // ---- layer 2 agg + relu + W3 dot (dynamic node loop — R8 form) --------------
    {
        float b2x = b2[2 * ln], b2y = b2[2 * ln + 1];
        float w3x = W3[2 * ln], w3y = W3[2 * ln + 1];
        for (int n = gw; n < NUM; n += 32){
            int e0 = sptr[n], e1 = sptr[n + 1];
            float a0 = 0.f, a1 = 0.f;
#pragma unroll 4
            for (int e = e0; e < e1; e++){
                int2  rc = meta[e];
                float c  = __int_as_float(rc.y);
                float2 hv = *(const float2*)(smraw + rc.x * ZSTR + 8 * ln);
                a0 += c * hv.x;
                a1 += c * hv.y;
            }
            a0 = fmaxf(a0 + b2x, 0.f);
            a1 = fmaxf(a1 + b2y, 0.f);
            float v = a0 * w3x + a1 * w3y;
#pragma unroll
            for (int o = 16; o > 0; o >>= 1) v += __shfl_xor_sync(0xffffffffu, v, o);
            if (ln == 0) t3[n] = v;
        }
    }
    __syncthreads();

    // ---- layer 3 aggregation: logits ----------------------------------------------
    if (t < NUM){
        float a = b3[0];
        int e0 = sptr[t], e1 = sptr[t + 1];
#pragma unroll 4
        for (int e = e0; e < e1; e++){
            int2 rc = meta[e];
            a += __int_as_float(rc.y) * t3[rc.x];
        }
        lg[t] = a;
    }
    __syncthreads();

    // ---- softmax over [0,10), sigmoid elsewhere ------------------------------------
    if (t < NUM){
        float v = lg[t];
        if (t < 32){
            float xv = (t < MAIN_N) ? v : -INFINITY;
            float m = xv;
#pragma unroll
            for (int o = 16; o > 0; o >>= 1) m = fmaxf(m, __shfl_xor_sync(0xffffffffu, m, o));
            float p = (t < MAIN_N) ? expf(xv - m) : 0.f;
            float s = p;
#pragma unroll
            for (int o = 16; o > 0; o >>= 1) s += __shfl_xor_sync(0xffffffffu, s, o);
            if (t < MAIN_N) out[b * NUM + t] = p / s;
        }
        if (t >= MAIN_N) out[b * NUM + t] = 1.f / (1.f + expf(-v));
    }
}

// ------------------------- launcher ------------------------------------------
extern "C" void kernel_launch(void* const* d_in, const int* in_sizes, int n_in,
                              void* d_out, int out_size)
{
    const float* x    = (const float*)d_in[0];
    const float* emb  = (const float*)d_in[1];
    const float* W1   = (const float*)d_in[2];
    const float* b1   = (const float*)d_in[3];
    const float* W2   = (const float*)d_in[4];
    const float* b2   = (const float*)d_in[5];
    const float* W3   = (const float*)d_in[6];
    const float* b3   = (const float*)d_in[7];
    const int*  erow  = (const int*)d_in[8];
    const int*  ecol  = (const int*)d_in[9];
    float* out = (float*)d_out;

    const int E = in_sizes[8];
    const int B = in_sizes[0] / NUM;

    cudaFuncSetAttribute(gcn_mega, cudaFuncAttributeMaxDynamicSharedMemorySize, SM_TOTAL);
    cudaFuncSetAttribute(prep_all, cudaFuncAttributeMaxDynamicSharedMemorySize, PS_TOTAL);

    prep_all<<<34, 1024, PS_TOTAL>>>(emb, W1, W2, erow, ecol, E);
    gcn_mega<<<B, THREADS, SM_TOTAL>>>(x, b1, b2, W3, b3, out);

    (void)n_in; (void)out_size;
}